// round 2
// baseline (speedup 1.0000x reference)
#include <cuda_runtime.h>
#include <cstdint>

#define NMAX 100000
#define DIM 128

// Scratch (allocation-free rule: __device__ globals)
__device__ __align__(16) float g_agg_in[(size_t)NMAX * DIM];
__device__ __align__(16) float g_agg_out[(size_t)NMAX * DIM];
__device__ float g_deg_in[NMAX];
__device__ float g_deg_out[NMAX];
__device__ float g_scale_in[NMAX];
__device__ float g_scale_out[NMAX];

__device__ __forceinline__ void red_add_v4(float* p, float4 v) {
    asm volatile("red.global.add.v4.f32 [%0], {%1,%2,%3,%4};"
                 :: "l"(p), "f"(v.x), "f"(v.y), "f"(v.z), "f"(v.w)
                 : "memory");
}

__device__ __forceinline__ int clamp_idx(int v, int n) {
    return v < 0 ? 0 : (v >= n ? n - 1 : v);
}

// ---------------------------------------------------------------------------
// Zero the accumulators + degree counters (must be deterministic each launch)
// ---------------------------------------------------------------------------
__global__ void zero_kernel(int n) {
    const float4 z = make_float4(0.f, 0.f, 0.f, 0.f);
    int total4 = n * (DIM / 4);
    int stride = gridDim.x * blockDim.x;
    for (int i = blockIdx.x * blockDim.x + threadIdx.x; i < total4; i += stride) {
        reinterpret_cast<float4*>(g_agg_in)[i]  = z;
        reinterpret_cast<float4*>(g_agg_out)[i] = z;
    }
    for (int i = blockIdx.x * blockDim.x + threadIdx.x; i < n; i += stride) {
        g_deg_in[i]  = 0.f;
        g_deg_out[i] = 0.f;
    }
}

// ---------------------------------------------------------------------------
// Degree counts (both directions). edge_index is int32 (JAX default x64 off).
// ---------------------------------------------------------------------------
__global__ void deg_kernel(const int* __restrict__ ei, int E, int n) {
    int e = blockIdx.x * blockDim.x + threadIdx.x;
    if (e >= E) return;
    int src = clamp_idx(__ldg(&ei[e]), n);
    int dst = clamp_idx(__ldg(&ei[E + e]), n);
    atomicAdd(&g_deg_in[dst],  1.f);
    atomicAdd(&g_deg_out[src], 1.f);
}

// ---------------------------------------------------------------------------
// Scale: fold mean-normalization and the 0.5 alpha weights into one factor
// ---------------------------------------------------------------------------
__global__ void scale_kernel(int n) {
    int i = blockIdx.x * blockDim.x + threadIdx.x;
    if (i >= n) return;
    g_scale_in[i]  = 0.5f / fmaxf(g_deg_in[i],  1.f);
    g_scale_out[i] = 0.5f / fmaxf(g_deg_out[i], 1.f);
}

// ---------------------------------------------------------------------------
// Scatter: one warp per edge, both directions. float4 vector atomics.
// ---------------------------------------------------------------------------
__global__ void scatter_kernel(const float* __restrict__ x,
                               const int* __restrict__ ei, int E, int n) {
    int warp = (blockIdx.x * blockDim.x + threadIdx.x) >> 5;
    int lane = threadIdx.x & 31;
    if (warp >= E) return;
    int src = clamp_idx(__ldg(&ei[warp]), n);
    int dst = clamp_idx(__ldg(&ei[E + warp]), n);

    // in-aggregation: x[src] -> agg_in[dst]
    float4 vs = reinterpret_cast<const float4*>(x + (size_t)src * DIM)[lane];
    red_add_v4(g_agg_in + (size_t)dst * DIM + lane * 4, vs);

    // out-aggregation: x[dst] -> agg_out[src]
    float4 vd = reinterpret_cast<const float4*>(x + (size_t)dst * DIM)[lane];
    red_add_v4(g_agg_out + (size_t)src * DIM + lane * 4, vd);
}

// ---------------------------------------------------------------------------
// Fused GEMM: out[N,128] = [x | s_in*agg_in | s_out*agg_out] (N x 384)
//                        @ [W_self ; W_s2d ; W_d2s] (384 x 128)  + bias
// BM=128, BN=128, BK=16, 256 threads, 8x8 per thread.
// ---------------------------------------------------------------------------
__global__ void __launch_bounds__(256, 2)
gemm_kernel(const float* __restrict__ x,
            const float* __restrict__ Wself, const float* __restrict__ bself,
            const float* __restrict__ Ws2d,  const float* __restrict__ bs2d,
            const float* __restrict__ Wd2s,  const float* __restrict__ bd2s,
            float* __restrict__ out, int n) {
    __shared__ float As[16][132];   // [k][m], padded row
    __shared__ float Bs[16][128];   // [k][n]

    const int block_row = blockIdx.x * 128;
    const int tid = threadIdx.x;
    const int tx = tid & 15;        // 0..15 -> output cols tx*8..tx*8+7
    const int ty = tid >> 4;        // 0..15 -> output rows ty*8..ty*8+7

    float acc[8][8];
#pragma unroll
    for (int i = 0; i < 8; i++)
#pragma unroll
        for (int j = 0; j < 8; j++) acc[i][j] = 0.f;

#pragma unroll 1
    for (int kt = 0; kt < 24; kt++) {
        const int k0 = kt * 16;

        // Select A source + per-row scale mode for this K tile
        const float* Abase;
        const float* srow;   // per-row scale array or null
        if (k0 < 128)       { Abase = x;         srow = nullptr; }
        else if (k0 < 256)  { Abase = g_agg_in;  srow = g_scale_in; }
        else                { Abase = g_agg_out; srow = g_scale_out; }
        const int klocal = k0 & 127;

        // Load A tile: 128 rows x 16 k = 512 float4, 2 per thread, transposed store
#pragma unroll
        for (int l = 0; l < 2; l++) {
            int id  = tid * 2 + l;        // 0..511
            int row = id >> 2;            // 0..127
            int c4  = (id & 3) * 4;       // 0,4,8,12 within the 16-k slab
            int grow = block_row + row;
            float4 v = make_float4(0.f, 0.f, 0.f, 0.f);
            if (grow < n) {
                v = *reinterpret_cast<const float4*>(
                        Abase + (size_t)grow * DIM + klocal + c4);
                if (srow) {
                    float s = srow[grow];
                    v.x *= s; v.y *= s; v.z *= s; v.w *= s;
                }
            }
            As[c4 + 0][row] = v.x;
            As[c4 + 1][row] = v.y;
            As[c4 + 2][row] = v.z;
            As[c4 + 3][row] = v.w;
        }

        // Load B tile: 16 k x 128 cols = 512 float4, 2 per thread
        const float* Wbase = (k0 < 128) ? (Wself + (size_t)k0 * 128)
                           : (k0 < 256) ? (Ws2d  + (size_t)(k0 - 128) * 128)
                                        : (Wd2s  + (size_t)(k0 - 256) * 128);
#pragma unroll
        for (int l = 0; l < 2; l++) {
            int id   = tid * 2 + l;       // 0..511
            int krow = id >> 5;           // 0..15
            int j4   = (id & 31) * 4;     // 0..124
            float4 v = *reinterpret_cast<const float4*>(Wbase + krow * 128 + j4);
            *reinterpret_cast<float4*>(&Bs[krow][j4]) = v;
        }

        __syncthreads();

#pragma unroll
        for (int kk = 0; kk < 16; kk++) {
            float a[8], b[8];
            *reinterpret_cast<float4*>(&a[0]) =
                *reinterpret_cast<const float4*>(&As[kk][ty * 8]);
            *reinterpret_cast<float4*>(&a[4]) =
                *reinterpret_cast<const float4*>(&As[kk][ty * 8 + 4]);
            *reinterpret_cast<float4*>(&b[0]) =
                *reinterpret_cast<const float4*>(&Bs[kk][tx * 8]);
            *reinterpret_cast<float4*>(&b[4]) =
                *reinterpret_cast<const float4*>(&Bs[kk][tx * 8 + 4]);
#pragma unroll
            for (int i = 0; i < 8; i++)
#pragma unroll
                for (int j = 0; j < 8; j++)
                    acc[i][j] += a[i] * b[j];
        }

        __syncthreads();
    }

    // Epilogue: fused bias = b_self + 0.5*b_s2d + 0.5*b_d2s
    float bias[8];
#pragma unroll
    for (int j = 0; j < 8; j++) {
        int col = tx * 8 + j;
        bias[j] = bself[col] + 0.5f * bs2d[col] + 0.5f * bd2s[col];
    }

#pragma unroll
    for (int i = 0; i < 8; i++) {
        int row = block_row + ty * 8 + i;
        if (row < n) {
            float* orow = out + (size_t)row * DIM + tx * 8;
            float4 v0 = make_float4(acc[i][0] + bias[0], acc[i][1] + bias[1],
                                    acc[i][2] + bias[2], acc[i][3] + bias[3]);
            float4 v1 = make_float4(acc[i][4] + bias[4], acc[i][5] + bias[5],
                                    acc[i][6] + bias[6], acc[i][7] + bias[7]);
            *reinterpret_cast<float4*>(orow)     = v0;
            *reinterpret_cast<float4*>(orow + 4) = v1;
        }
    }
}

// ---------------------------------------------------------------------------
// Launch
// ---------------------------------------------------------------------------
extern "C" void kernel_launch(void* const* d_in, const int* in_sizes, int n_in,
                              void* d_out, int out_size) {
    const float* x     = (const float*)d_in[0];
    const float* Wself = (const float*)d_in[1];
    const float* bself = (const float*)d_in[2];
    const float* Ws2d  = (const float*)d_in[3];
    const float* bs2d  = (const float*)d_in[4];
    const float* Wd2s  = (const float*)d_in[5];
    const float* bd2s  = (const float*)d_in[6];
    const int*   ei    = (const int*)d_in[7];   // int32: JAX default (x64 disabled)

    int N = in_sizes[0] / DIM;      // 100000
    int E = in_sizes[7] / 2;        // 800000
    float* out = (float*)d_out;

    zero_kernel<<<1024, 256>>>(N);

    deg_kernel<<<(E + 255) / 256, 256>>>(ei, E, N);

    // one warp per edge
    int scatter_blocks = (E * 32 + 255) / 256;
    scatter_kernel<<<scatter_blocks, 256>>>(x, ei, E, N);

    scale_kernel<<<(N + 255) / 256, 256>>>(N);

    gemm_kernel<<<(N + 127) / 128, 256>>>(x, Wself, bself, Ws2d, bs2d,
                                          Wd2s, bd2s, out, N);
}

// round 4
// speedup vs baseline: 1.2722x; 1.2722x over previous
#include <cuda_runtime.h>
#include <cuda_bf16.h>
#include <cstdint>

#define NMAX 100000
#define DIM 128

// ---------------------------------------------------------------------------
// Scratch (__device__ globals per allocation-free rule)
// ---------------------------------------------------------------------------
__device__ __align__(16) float g_agg_in[(size_t)NMAX * DIM];
__device__ __align__(16) float g_agg_out[(size_t)NMAX * DIM];
__device__ float g_deg_in[NMAX];
__device__ float g_deg_out[NMAX];
__device__ float g_scale_in[NMAX];
__device__ float g_scale_out[NMAX];
// Weights, bf16 split, TRANSPOSED to [chunk][n][k]  (B[n][k] = W[k][n])
__device__ __align__(16) __nv_bfloat16 g_Bhi[3 * 128 * 128];
__device__ __align__(16) __nv_bfloat16 g_Blo[3 * 128 * 128];

// ---------------------------------------------------------------------------
// helpers
// ---------------------------------------------------------------------------
__device__ __forceinline__ void red_add_v4(float* p, float4 v) {
    asm volatile("red.global.add.v4.f32 [%0], {%1,%2,%3,%4};"
                 :: "l"(p), "f"(v.x), "f"(v.y), "f"(v.z), "f"(v.w)
                 : "memory");
}

__device__ __forceinline__ int clamp_idx(int v, int n) {
    return v < 0 ? 0 : (v >= n ? n - 1 : v);
}

__device__ __forceinline__ uint32_t smem_u32(const void* p) {
    uint32_t a;
    asm("{ .reg .u64 t; cvta.to.shared.u64 t, %1; cvt.u32.u64 %0, t; }"
        : "=r"(a) : "l"(p));
    return a;
}

__device__ __forceinline__ void ldsm_x4(uint32_t* r, uint32_t addr) {
    asm volatile("ldmatrix.sync.aligned.m8n8.x4.shared.b16 {%0,%1,%2,%3}, [%4];"
                 : "=r"(r[0]), "=r"(r[1]), "=r"(r[2]), "=r"(r[3]) : "r"(addr));
}

__device__ __forceinline__ void mma_bf16(float* d, const uint32_t* a,
                                         uint32_t b0, uint32_t b1) {
    asm volatile(
        "mma.sync.aligned.m16n8k16.row.col.f32.bf16.bf16.f32 "
        "{%0,%1,%2,%3}, {%4,%5,%6,%7}, {%8,%9}, {%0,%1,%2,%3};"
        : "+f"(d[0]), "+f"(d[1]), "+f"(d[2]), "+f"(d[3])
        : "r"(a[0]), "r"(a[1]), "r"(a[2]), "r"(a[3]), "r"(b0), "r"(b1));
}

// ---------------------------------------------------------------------------
// Zero accumulators + degree counters
// ---------------------------------------------------------------------------
__global__ void zero_kernel(int n) {
    const float4 z = make_float4(0.f, 0.f, 0.f, 0.f);
    int total4 = n * (DIM / 4);
    int stride = gridDim.x * blockDim.x;
    for (int i = blockIdx.x * blockDim.x + threadIdx.x; i < total4; i += stride) {
        reinterpret_cast<float4*>(g_agg_in)[i]  = z;
        reinterpret_cast<float4*>(g_agg_out)[i] = z;
    }
    for (int i = blockIdx.x * blockDim.x + threadIdx.x; i < n; i += stride) {
        g_deg_in[i]  = 0.f;
        g_deg_out[i] = 0.f;
    }
}

// ---------------------------------------------------------------------------
// Degree counts (edge_index is int32)
// ---------------------------------------------------------------------------
__global__ void deg_kernel(const int* __restrict__ ei, int E, int n) {
    int e = blockIdx.x * blockDim.x + threadIdx.x;
    if (e >= E) return;
    int src = clamp_idx(__ldg(&ei[e]), n);
    int dst = clamp_idx(__ldg(&ei[E + e]), n);
    atomicAdd(&g_deg_in[dst],  1.f);
    atomicAdd(&g_deg_out[src], 1.f);
}

__global__ void scale_kernel(int n) {
    int i = blockIdx.x * blockDim.x + threadIdx.x;
    if (i >= n) return;
    g_scale_in[i]  = 0.5f / fmaxf(g_deg_in[i],  1.f);
    g_scale_out[i] = 0.5f / fmaxf(g_deg_out[i], 1.f);
}

// ---------------------------------------------------------------------------
// Weight prep: split fp32 W[k][n] -> bf16 hi/lo, transposed to [n][k]
// ---------------------------------------------------------------------------
__global__ void prep_weights(const float* __restrict__ Wself,
                             const float* __restrict__ Ws2d,
                             const float* __restrict__ Wd2s) {
    int idx = blockIdx.x * blockDim.x + threadIdx.x;
    if (idx >= 3 * 16384) return;
    int chunk = idx >> 14;
    int rem   = idx & 16383;
    int k  = rem >> 7;
    int nn = rem & 127;
    const float* W = (chunk == 0) ? Wself : (chunk == 1) ? Ws2d : Wd2s;
    float w = __ldg(&W[k * 128 + nn]);
    __nv_bfloat16 hi = __float2bfloat16(w);
    float lo = w - __bfloat162float(hi);
    g_Bhi[chunk * 16384 + nn * 128 + k] = hi;
    g_Blo[chunk * 16384 + nn * 128 + k] = __float2bfloat16(lo);
}

// ---------------------------------------------------------------------------
// Scatter: one warp per edge, both directions, v4 atomics
// ---------------------------------------------------------------------------
__global__ void scatter_kernel(const float* __restrict__ x,
                               const int* __restrict__ ei, int E, int n) {
    int warp = (blockIdx.x * blockDim.x + threadIdx.x) >> 5;
    int lane = threadIdx.x & 31;
    if (warp >= E) return;
    int src = clamp_idx(__ldg(&ei[warp]), n);
    int dst = clamp_idx(__ldg(&ei[E + warp]), n);

    float4 vs = reinterpret_cast<const float4*>(x + (size_t)src * DIM)[lane];
    red_add_v4(g_agg_in + (size_t)dst * DIM + lane * 4, vs);

    float4 vd = reinterpret_cast<const float4*>(x + (size_t)dst * DIM)[lane];
    red_add_v4(g_agg_out + (size_t)src * DIM + lane * 4, vd);
}

// ---------------------------------------------------------------------------
// Tensor-core GEMM via mma.sync (bf16 3-term split):
//   out[N,128] = [x | s_in*agg_in | s_out*agg_out] (N x 384) @ W (384x128) + b
// BM=128, BN=128; 8 warps; warp tile 32x64; K processed in 3 chunks of 128.
// SMEM: A_hi/A_lo/B_hi/B_lo bf16 tiles, 128 rows x 136 bf16 (272B padded).
// ---------------------------------------------------------------------------
#define TSTRIDE 272   // bytes per padded row (136 bf16)
#define TBYTES  (128 * TSTRIDE)

__global__ void __launch_bounds__(256, 1)
gemm_mma_kernel(const float* __restrict__ x,
                const float* __restrict__ bself,
                const float* __restrict__ bs2d,
                const float* __restrict__ bd2s,
                float* __restrict__ out, int n) {
    extern __shared__ char smem[];
    char* pA_hi = smem;
    char* pA_lo = smem + TBYTES;
    char* pB_hi = smem + 2 * TBYTES;
    char* pB_lo = smem + 3 * TBYTES;
    const uint32_t sA_hi = smem_u32(pA_hi);
    const uint32_t sA_lo = sA_hi + TBYTES;
    const uint32_t sB_hi = sA_hi + 2 * TBYTES;
    const uint32_t sB_lo = sA_hi + 3 * TBYTES;

    const int tid  = threadIdx.x;
    const int lane = tid & 31;
    const int wid  = tid >> 5;
    const int block_row = blockIdx.x * 128;

    // warp tile: 32 rows x 64 cols
    const int m0 = (wid & 3) * 32;
    const int n0 = (wid >> 2) * 64;

    // fill-thread mapping: 2 threads per row, each handles a 64-col half
    const int frow = tid >> 1;
    const int half = tid & 1;
    const int grow = min(block_row + frow, n - 1);

    // ldmatrix per-lane base offsets (bytes)
    // A (16x16 frag at (m,k)): row = m + (lane&15), colByte = ((lane>>4)*8)*2
    const uint32_t offA = (uint32_t)(m0 + (lane & 15)) * TSTRIDE + ((lane >> 4) << 4);
    // B (n16xk16 x4 at (nb,k)): row = nb + ((lane>>4)<<3) + (lane&7),
    //                           colByte = (((lane>>3)&1)*8)*2
    const uint32_t offB = (uint32_t)(n0 + ((lane >> 4) << 3) + (lane & 7)) * TSTRIDE
                        + (((lane >> 3) & 1) << 4);

    float acc[2][8][4];
#pragma unroll
    for (int m = 0; m < 2; m++)
#pragma unroll
        for (int f = 0; f < 8; f++)
#pragma unroll
            for (int r = 0; r < 4; r++) acc[m][f][r] = 0.f;

#pragma unroll 1
    for (int chunk = 0; chunk < 3; chunk++) {
        // ---- A tile: fp32 load, scale, split, store hi/lo bf16
        const float* Abase = (chunk == 0) ? x
                           : (chunk == 1) ? g_agg_in : g_agg_out;
        float s = 1.0f;
        if (chunk == 1) s = g_scale_in[grow];
        else if (chunk == 2) s = g_scale_out[grow];

        const float4* arow = reinterpret_cast<const float4*>(
            Abase + (size_t)grow * DIM + half * 64);
        char* dst_hi = pA_hi + frow * TSTRIDE + half * 128;
        char* dst_lo = pA_lo + frow * TSTRIDE + half * 128;
#pragma unroll
        for (int j = 0; j < 16; j++) {
            float4 v = __ldg(&arow[j]);
            v.x *= s; v.y *= s; v.z *= s; v.w *= s;
            __nv_bfloat16 hx = __float2bfloat16(v.x);
            __nv_bfloat16 hy = __float2bfloat16(v.y);
            __nv_bfloat16 hz = __float2bfloat16(v.z);
            __nv_bfloat16 hw = __float2bfloat16(v.w);
            __nv_bfloat162 h01; h01.x = hx; h01.y = hy;
            __nv_bfloat162 h23; h23.x = hz; h23.y = hw;
            __nv_bfloat162 l01;
            l01.x = __float2bfloat16(v.x - __bfloat162float(hx));
            l01.y = __float2bfloat16(v.y - __bfloat162float(hy));
            __nv_bfloat162 l23;
            l23.x = __float2bfloat16(v.z - __bfloat162float(hz));
            l23.y = __float2bfloat16(v.w - __bfloat162float(hw));
            *reinterpret_cast<uint2*>(dst_hi + j * 8) =
                make_uint2(*reinterpret_cast<uint32_t*>(&h01),
                           *reinterpret_cast<uint32_t*>(&h23));
            *reinterpret_cast<uint2*>(dst_lo + j * 8) =
                make_uint2(*reinterpret_cast<uint32_t*>(&l01),
                           *reinterpret_cast<uint32_t*>(&l23));
        }

        // ---- B tile: copy pre-split bf16 weights
        {
            const uint4* bh = reinterpret_cast<const uint4*>(
                g_Bhi + chunk * 16384 + frow * 128 + half * 64);
            const uint4* bl = reinterpret_cast<const uint4*>(
                g_Blo + chunk * 16384 + frow * 128 + half * 64);
            char* db_hi = pB_hi + frow * TSTRIDE + half * 128;
            char* db_lo = pB_lo + frow * TSTRIDE + half * 128;
#pragma unroll
            for (int j = 0; j < 8; j++) {
                *reinterpret_cast<uint4*>(db_hi + j * 16) = __ldg(&bh[j]);
                *reinterpret_cast<uint4*>(db_lo + j * 16) = __ldg(&bl[j]);
            }
        }

        __syncthreads();

        // ---- MMA mainloop: 8 k16-steps
#pragma unroll 2
        for (int ks = 0; ks < 8; ks++) {
            const uint32_t kb = (uint32_t)ks * 32;   // k16 * 2 bytes

            uint32_t ah[2][4], al[2][4];
#pragma unroll
            for (int m = 0; m < 2; m++) {
                uint32_t a = offA + (uint32_t)m * 16 * TSTRIDE + kb;
                ldsm_x4(ah[m], sA_hi + a);
                ldsm_x4(al[m], sA_lo + a);
            }
#pragma unroll
            for (int g = 0; g < 4; g++) {            // n16 groups
                uint32_t b = offB + (uint32_t)g * 16 * TSTRIDE + kb;
                uint32_t bh[4], bl[4];
                ldsm_x4(bh, sB_hi + b);
                ldsm_x4(bl, sB_lo + b);
#pragma unroll
                for (int m = 0; m < 2; m++) {
                    mma_bf16(acc[m][2 * g + 0], ah[m], bh[0], bh[1]);
                    mma_bf16(acc[m][2 * g + 1], ah[m], bh[2], bh[3]);
                    mma_bf16(acc[m][2 * g + 0], ah[m], bl[0], bl[1]);
                    mma_bf16(acc[m][2 * g + 1], ah[m], bl[2], bl[3]);
                    mma_bf16(acc[m][2 * g + 0], al[m], bh[0], bh[1]);
                    mma_bf16(acc[m][2 * g + 1], al[m], bh[2], bh[3]);
                }
            }
        }

        __syncthreads();
    }

    // ---- Epilogue: fused bias = b_self + 0.5*(b_s2d + b_d2s)
    const int colq = (lane & 3) * 2;       // 0,2,4,6
    const int rowq = lane >> 2;            // 0..7
#pragma unroll
    for (int f = 0; f < 8; f++) {
        int col = n0 + f * 8 + colq;
        float b0 = __ldg(&bself[col])     + 0.5f * (__ldg(&bs2d[col])     + __ldg(&bd2s[col]));
        float b1 = __ldg(&bself[col + 1]) + 0.5f * (__ldg(&bs2d[col + 1]) + __ldg(&bd2s[col + 1]));
#pragma unroll
        for (int m = 0; m < 2; m++) {
            int r0 = block_row + m0 + m * 16 + rowq;
#pragma unroll
            for (int h = 0; h < 2; h++) {       // d0d1 (row), d2d3 (row+8)
                int row = r0 + h * 8;
                if (row < n) {
                    float2 v = make_float2(acc[m][f][2 * h] + b0,
                                           acc[m][f][2 * h + 1] + b1);
                    *reinterpret_cast<float2*>(out + (size_t)row * DIM + col) = v;
                }
            }
        }
    }
}

// ---------------------------------------------------------------------------
// Launch
// ---------------------------------------------------------------------------
extern "C" void kernel_launch(void* const* d_in, const int* in_sizes, int n_in,
                              void* d_out, int out_size) {
    const float* x     = (const float*)d_in[0];
    const float* Wself = (const float*)d_in[1];
    const float* bself = (const float*)d_in[2];
    const float* Ws2d  = (const float*)d_in[3];
    const float* bs2d  = (const float*)d_in[4];
    const float* Wd2s  = (const float*)d_in[5];
    const float* bd2s  = (const float*)d_in[6];
    const int*   ei    = (const int*)d_in[7];

    int N = in_sizes[0] / DIM;      // 100000
    int E = in_sizes[7] / 2;        // 800000
    float* out = (float*)d_out;

    const int smem_bytes = 4 * TBYTES;   // 139264
    cudaFuncSetAttribute(gemm_mma_kernel,
                         cudaFuncAttributeMaxDynamicSharedMemorySize, smem_bytes);

    zero_kernel<<<2048, 256>>>(N);
    prep_weights<<<(3 * 16384 + 255) / 256, 256>>>(Wself, Ws2d, Wd2s);
    deg_kernel<<<(E + 255) / 256, 256>>>(ei, E, N);

    int scatter_blocks = (E * 32 + 255) / 256;
    scatter_kernel<<<scatter_blocks, 256>>>(x, ei, E, N);

    scale_kernel<<<(N + 255) / 256, 256>>>(N);

    gemm_mma_kernel<<<(N + 127) / 128, 256, smem_bytes>>>(x, bself, bs2d, bd2s,
                                                          out, N);
}